// round 10
// baseline (speedup 1.0000x reference)
#include <cuda_runtime.h>
#include <cuda_fp16.h>
#include <stdint.h>
#include <math.h>

#define T_TOK 1024
#define DIN   2048
#define NH    32
#define NKV   8
#define HD    64

__device__ float g_q[T_TOK * NH * HD];
__device__ float g_k[T_TOK * NKV * HD];
__device__ __half g_qa[T_TOK * NH * HD];   // fp16 q (scaled by 0.125)
__device__ __half g_ka[T_TOK * NKV * HD];  // fp16 k
__device__ __half g_va[T_TOK * NKV * HD];  // fp16 v (from GEMM epilogue)
__device__ __half g_xh[T_TOK * DIN];
__device__ __half g_wqh[NH * HD * DIN];
__device__ __half g_wkh[NKV * HD * DIN];
__device__ __half g_wvh[NKV * HD * DIN];
__device__ __half g_woh[DIN * NH * HD];
__device__ __half g_abh[T_TOK * NH * HD];
// split-KV partials
__device__ float g_po0[T_TOK * NH * HD];
__device__ float g_po1[T_TOK * NH * HD];
__device__ float g_pm0[T_TOK * NH];
__device__ float g_pm1[T_TOK * NH];
__device__ float g_pl0[T_TOK * NH];
__device__ float g_pl1[T_TOK * NH];

// ---------------------------------------------------------------------------
// asm helpers
// ---------------------------------------------------------------------------
__device__ __forceinline__ uint32_t smem_u32(const void* p) {
    uint32_t a;
    asm("{ .reg .u64 t; cvta.to.shared.u64 t, %1; cvt.u32.u64 %0, t; }"
        : "=r"(a) : "l"(p));
    return a;
}

__device__ __forceinline__ void mma_f16(float* c, const uint32_t* a,
                                        const uint32_t* b) {
    asm volatile(
        "mma.sync.aligned.m16n8k16.row.col.f32.f16.f16.f32 "
        "{%0,%1,%2,%3},{%4,%5,%6,%7},{%8,%9},{%0,%1,%2,%3};"
        : "+f"(c[0]), "+f"(c[1]), "+f"(c[2]), "+f"(c[3])
        : "r"(a[0]), "r"(a[1]), "r"(a[2]), "r"(a[3]), "r"(b[0]), "r"(b[1]));
}

__device__ __forceinline__ void ldsm_x4(uint32_t* r, uint32_t addr) {
    asm volatile(
        "ldmatrix.sync.aligned.m8n8.x4.shared.b16 {%0,%1,%2,%3}, [%4];"
        : "=r"(r[0]), "=r"(r[1]), "=r"(r[2]), "=r"(r[3]) : "r"(addr));
}

__device__ __forceinline__ void ldsm_x4_t(uint32_t* r, uint32_t addr) {
    asm volatile(
        "ldmatrix.sync.aligned.m8n8.x4.trans.shared.b16 {%0,%1,%2,%3}, [%4];"
        : "=r"(r[0]), "=r"(r[1]), "=r"(r[2]), "=r"(r[3]) : "r"(addr));
}

__device__ __forceinline__ void cp16(uint32_t d, const void* s) {
    asm volatile("cp.async.cg.shared.global [%0], [%1], 16;"
                 :: "r"(d), "l"(s));
}
__device__ __forceinline__ void cp_commit() {
    asm volatile("cp.async.commit_group;");
}
template <int N>
__device__ __forceinline__ void cp_wait() {
    asm volatile("cp.async.wait_group %0;" :: "n"(N));
}

__device__ __forceinline__ uint32_t h2pack(float a, float b) {
    __half2 h = __floats2half2_rn(a, b);
    return *(uint32_t*)&h;
}

#define SW128(o) ((o) ^ (((o) >> 3) & 0x70))

// ---------------------------------------------------------------------------
// fp32 -> fp16 convert (x, Wq, Wk, Wv, Wo): 12M elems, 8 per thread.
// ---------------------------------------------------------------------------
__global__ __launch_bounds__(256) void cvt_all(const float* __restrict__ x,
                                               const float* __restrict__ Wq,
                                               const float* __restrict__ Wk,
                                               const float* __restrict__ Wv,
                                               const float* __restrict__ Wo) {
    const size_t e = ((size_t)blockIdx.x * 256 + threadIdx.x) * 8;
    const float* src;
    __half* dst;
    size_t base;
    if (e < 2097152)        { src = x;  dst = g_xh;  base = 0; }
    else if (e < 6291456)   { src = Wq; dst = g_wqh; base = 2097152; }
    else if (e < 7340032)   { src = Wk; dst = g_wkh; base = 6291456; }
    else if (e < 8388608)   { src = Wv; dst = g_wvh; base = 7340032; }
    else                    { src = Wo; dst = g_woh; base = 8388608; }
    const size_t o = e - base;
#pragma unroll
    for (int p = 0; p < 2; p++) {
        float4 v = *(const float4*)&src[o + p * 4];
        *(__half2*)&dst[o + p * 4]     = __floats2half2_rn(v.x, v.y);
        *(__half2*)&dst[o + p * 4 + 2] = __floats2half2_rn(v.z, v.w);
    }
}

// ---------------------------------------------------------------------------
// fp16 GEMM via cp.async + ldmatrix (R7 config: 2-stage, 64KB).
// ---------------------------------------------------------------------------
__device__ __forceinline__ void gemm_tile_h(const __half* __restrict__ A,
                                            const __half* __restrict__ B,
                                            float* __restrict__ C,
                                            __half* __restrict__ Ch,
                                            int N, int K, int bm, int bn,
                                            char* smem) {
    const uint32_t sbase = smem_u32(smem);
    const int tid  = threadIdx.x;
    const int lane = tid & 31;
    const int warp = tid >> 5;
    const int g    = lane >> 2;
    const int tq   = lane & 3;
    const int wm   = warp & 1;
    const int wn   = warp >> 1;
    const int quad = lane >> 3;
    const int lr   = lane & 7;
    const int ldrow = tid >> 3;
    const int ldc16 = tid & 7;

    auto stage = [&](int k0, int buf) {
        uint32_t dA = sbase + buf * 32768;
        uint32_t dB = dA + 16384;
#pragma unroll
        for (int p = 0; p < 4; p++) {
            int r = ldrow + p * 32;
            cp16(dA + SW128(r * 128 + ldc16 * 16),
                 &A[(size_t)(bm + r) * K + k0 + ldc16 * 8]);
            cp16(dB + SW128(r * 128 + ldc16 * 16),
                 &B[(size_t)(bn + r) * K + k0 + ldc16 * 8]);
        }
    };

    float acc[4][4][4];
#pragma unroll
    for (int mi = 0; mi < 4; mi++)
#pragma unroll
        for (int ni = 0; ni < 4; ni++)
#pragma unroll
            for (int r = 0; r < 4; r++) acc[mi][ni][r] = 0.0f;

    stage(0, 0);
    cp_commit();
    stage(64, 1);
    cp_commit();

    const int nch = K >> 6;
    for (int c = 0; c < nch; c++) {
        if (c == nch - 1) cp_wait<0>(); else cp_wait<1>();
        __syncthreads();
        const uint32_t sA = sbase + (c & 1) * 32768;
        const uint32_t sB = sA + 16384;

#pragma unroll
        for (int ks = 0; ks < 4; ks++) {
            uint32_t af[4][4];
#pragma unroll
            for (int mi = 0; mi < 4; mi++) {
                int row = wm * 64 + mi * 16 + (quad & 1) * 8 + lr;
                int colb = ks * 32 + (quad >> 1) * 16;
                ldsm_x4(af[mi], sA + SW128(row * 128 + colb));
            }
            uint32_t bf[2][4];
#pragma unroll
            for (int np = 0; np < 2; np++) {
                int row = wn * 32 + np * 16 + (quad >> 1) * 8 + lr;
                int colb = ks * 32 + (quad & 1) * 16;
                ldsm_x4(bf[np], sB + SW128(row * 128 + colb));
            }
#pragma unroll
            for (int mi = 0; mi < 4; mi++)
#pragma unroll
                for (int ni = 0; ni < 4; ni++)
                    mma_f16(acc[mi][ni], af[mi], &bf[ni >> 1][(ni & 1) * 2]);
        }

        if (c + 2 < nch) {
            __syncthreads();
            stage((c + 2) << 6, c & 1);
            cp_commit();
        }
    }

#pragma unroll
    for (int mi = 0; mi < 4; mi++)
#pragma unroll
        for (int ni = 0; ni < 4; ni++) {
            const int row = bm + wm * 64 + mi * 16 + g;
            const int col = bn + wn * 32 + ni * 8 + tq * 2;
            if (Ch) {
                *(__half2*)&Ch[(size_t)row * N + col] =
                    __floats2half2_rn(acc[mi][ni][0], acc[mi][ni][1]);
                *(__half2*)&Ch[(size_t)(row + 8) * N + col] =
                    __floats2half2_rn(acc[mi][ni][2], acc[mi][ni][3]);
            } else {
                *(float2*)&C[(size_t)row * N + col] =
                    make_float2(acc[mi][ni][0], acc[mi][ni][1]);
                *(float2*)&C[(size_t)(row + 8) * N + col] =
                    make_float2(acc[mi][ni][2], acc[mi][ni][3]);
            }
        }
}

__global__ __launch_bounds__(256) void gemm_h(const __half* __restrict__ A,
                                              const __half* __restrict__ B,
                                              float* __restrict__ C,
                                              int N, int K) {
    extern __shared__ char sh[];
    gemm_tile_h(A, B, C, nullptr, N, K, blockIdx.y * 128, blockIdx.x * 128, sh);
}

// Fused QKV: bx<16 -> Wq (fp32 out), bx<20 -> Wk (fp32), else Wv (fp16 out)
__global__ __launch_bounds__(256) void gemm_qkv_h(float* __restrict__ qb,
                                                  float* __restrict__ kb) {
    extern __shared__ char sh[];
    const int bx = blockIdx.x;
    const __half* B;
    float* C = nullptr;
    __half* Ch = nullptr;
    int N, bn;
    if (bx < 16)      { B = g_wqh; C = qb;  N = 2048; bn = bx * 128; }
    else if (bx < 20) { B = g_wkh; C = kb;  N = 512;  bn = (bx - 16) * 128; }
    else              { B = g_wvh; Ch = g_va; N = 512; bn = (bx - 20) * 128; }
    gemm_tile_h(g_xh, B, C, Ch, N, 2048, blockIdx.y * 128, bn, sh);
}

// ---------------------------------------------------------------------------
// RMSNorm + RoPE; reads fp32 q/k, writes fp16 (q scaled by 1/8).
// ---------------------------------------------------------------------------
__global__ __launch_bounds__(256) void norm_rope2(const float* __restrict__ qb,
                                                  const float* __restrict__ kb,
                                                  const float* __restrict__ qw,
                                                  const float* __restrict__ kw,
                                                  const float* __restrict__ cosb,
                                                  const float* __restrict__ sinb) {
    const int t = blockIdx.x;
    const int warp = threadIdx.x >> 5;
    const int lane = threadIdx.x & 31;
    const bool isk = (blockIdx.y == 4);
    const int h = isk ? warp : blockIdx.y * 8 + warp;
    const int nheads = isk ? NKV : NH;
    const float* w = isk ? kw : qw;
    const float* buf = isk ? kb : qb;
    __half* outh = isk ? g_ka : g_qa;
    const float sc = isk ? 1.0f : 0.125f;

    const float* p = buf + (size_t)t * nheads * HD + h * HD;
    float a = p[lane];
    float b = p[lane + 32];

    float ss = a * a + b * b;
#pragma unroll
    for (int o = 16; o; o >>= 1) ss += __shfl_xor_sync(0xffffffffu, ss, o);
    float inv = rsqrtf(ss * (1.0f / HD) + 1e-6f);

    a *= inv * w[lane];
    b *= inv * w[lane + 32];

    float c0 = cosb[t * HD + lane];
    float s0 = sinb[t * HD + lane];
    float c1 = cosb[t * HD + lane + 32];
    float s1 = sinb[t * HD + lane + 32];

    __half* po = outh + (size_t)t * nheads * HD + h * HD;
    po[lane]      = __float2half((a * c0 - b * s0) * sc);
    po[lane + 32] = __float2half((b * c1 + a * s1) * sc);
}

// ---------------------------------------------------------------------------
// Split-KV fp16 flash attention.
// grid (2 splits, 32 heads, 16 qtiles); qt = 15 - blockIdx.z (big first).
// split0: kv steps 0..min(qt,7); split1: steps 8..qt (only qt>=8).
// Writes unnormalized fp32 O partials + per-row (m, l).
// ---------------------------------------------------------------------------
__global__ __launch_bounds__(128) void attn_h() {
    const int split = blockIdx.x;
    const int h  = blockIdx.y;
    const int qt = 15 - blockIdx.z;
    if (split == 1 && qt < 8) return;
    const int s0 = split ? 8 : 0;
    const int s1 = split ? qt : min(qt, 7);

    extern __shared__ char sm[];
    const uint32_t sbase = smem_u32(sm);
    const uint32_t sQ = sbase;

    const int kvh = h >> 2;
    const int tid = threadIdx.x;
    const int lane = tid & 31;
    const int warp = tid >> 5;
    const int g = lane >> 2;
    const int tq = lane & 3;
    const int quad = lane >> 3;
    const int lr = lane & 7;
    const int wr = warp * 16;
    const int row0 = wr + g;
    const int row1 = wr + 8 + g;

    // stage Q tile
    {
        const __half* qp = g_qa + (size_t)(qt * 64) * (NH * HD) + h * HD;
#pragma unroll
        for (int l = 0; l < 4; l++) {
            int idx = tid + l * 128;
            int r = idx >> 3;
            int c16 = idx & 7;
            cp16(sQ + SW128(r * 128 + c16 * 16),
                 &qp[(size_t)r * (NH * HD) + c16 * 8]);
        }
    }
    cp_commit();

    auto stageKV = [&](int s, int buf) {
        uint32_t dK = sbase + 8192 + buf * 16384;
        uint32_t dV = dK + 8192;
        const __half* kp = g_ka + (size_t)(s * 64) * (NKV * HD) + kvh * HD;
        const __half* vp = g_va + (size_t)(s * 64) * (NKV * HD) + kvh * HD;
#pragma unroll
        for (int l = 0; l < 4; l++) {
            int idx = tid + l * 128;
            int c = idx >> 3;
            int c16 = idx & 7;
            uint32_t off = SW128(c * 128 + c16 * 16);
            cp16(dK + off, &kp[(size_t)c * (NKV * HD) + c16 * 8]);
            cp16(dV + off, &vp[(size_t)c * (NKV * HD) + c16 * 8]);
        }
    };

    stageKV(s0, s0 & 1);
    cp_commit();
    if (s0 < s1) {
        stageKV(s0 + 1, (s0 + 1) & 1);
        cp_commit();
    }

    if (s0 < s1) cp_wait<2>(); else cp_wait<1>();
    __syncthreads();
    uint32_t qf[4][4];
#pragma unroll
    for (int ks = 0; ks < 4; ks++) {
        int row = wr + (quad & 1) * 8 + lr;
        int colb = ks * 32 + (quad >> 1) * 16;
        ldsm_x4(qf[ks], sQ + SW128(row * 128 + colb));
    }

    float m0 = -1e30f, m1 = -1e30f, l0 = 0.0f, l1 = 0.0f;
    float oacc[8][4];
#pragma unroll
    for (int nt = 0; nt < 8; nt++)
#pragma unroll
        for (int r = 0; r < 4; r++) oacc[nt][r] = 0.0f;

    for (int s = s0; s <= s1; s++) {
        if (s == s1) cp_wait<0>(); else cp_wait<1>();
        __syncthreads();
        const uint32_t sK = sbase + 8192 + (s & 1) * 16384;
        const uint32_t sV = sK + 8192;

        float sa[8][4];
#pragma unroll
        for (int nt = 0; nt < 8; nt++)
#pragma unroll
            for (int r = 0; r < 4; r++) sa[nt][r] = 0.0f;
#pragma unroll
        for (int ks = 0; ks < 4; ks++) {
#pragma unroll
            for (int np = 0; np < 4; np++) {
                uint32_t kb[4];
                int row = np * 16 + (quad >> 1) * 8 + lr;
                int colb = ks * 32 + (quad & 1) * 16;
                ldsm_x4(kb, sK + SW128(row * 128 + colb));
                mma_f16(sa[np * 2], qf[ks], &kb[0]);
                mma_f16(sa[np * 2 + 1], qf[ks], &kb[2]);
            }
        }

        const bool diag = (s == qt);
        float rm0 = -1e30f, rm1 = -1e30f;
#pragma unroll
        for (int nt = 0; nt < 8; nt++) {
            int c0i = nt * 8 + 2 * tq;
            if (diag) {
#pragma unroll
                for (int j = 0; j < 2; j++) {
                    if (c0i + j > row0) sa[nt][j] = -1e30f;
                    if (c0i + j > row1) sa[nt][2 + j] = -1e30f;
                }
            }
            rm0 = fmaxf(rm0, fmaxf(sa[nt][0], sa[nt][1]));
            rm1 = fmaxf(rm1, fmaxf(sa[nt][2], sa[nt][3]));
        }
#pragma unroll
        for (int o = 1; o < 4; o <<= 1) {
            rm0 = fmaxf(rm0, __shfl_xor_sync(0xffffffffu, rm0, o));
            rm1 = fmaxf(rm1, __shfl_xor_sync(0xffffffffu, rm1, o));
        }
        float nm0 = fmaxf(m0, rm0), nm1 = fmaxf(m1, rm1);
        float cr0 = __expf(m0 - nm0), cr1 = __expf(m1 - nm1);
        m0 = nm0; m1 = nm1;
        float rs0 = 0.0f, rs1 = 0.0f;
        uint32_t pr2[8][2];
#pragma unroll
        for (int nt = 0; nt < 8; nt++) {
            float p0 = __expf(sa[nt][0] - m0);
            float p1 = __expf(sa[nt][1] - m0);
            float p2 = __expf(sa[nt][2] - m1);
            float p3 = __expf(sa[nt][3] - m1);
            rs0 += p0 + p1;
            rs1 += p2 + p3;
            pr2[nt][0] = h2pack(p0, p1);
            pr2[nt][1] = h2pack(p2, p3);
        }
#pragma unroll
        for (int o = 1; o < 4; o <<= 1) {
            rs0 += __shfl_xor_sync(0xffffffffu, rs0, o);
            rs1 += __shfl_xor_sync(0xffffffffu, rs1, o);
        }
        l0 = l0 * cr0 + rs0;
        l1 = l1 * cr1 + rs1;
#pragma unroll
        for (int nt = 0; nt < 8; nt++) {
            oacc[nt][0] *= cr0; oacc[nt][1] *= cr0;
            oacc[nt][2] *= cr1; oacc[nt][3] *= cr1;
        }

#pragma unroll
        for (int ks = 0; ks < 4; ks++) {
            uint32_t af[4] = {pr2[2 * ks][0], pr2[2 * ks][1],
                              pr2[2 * ks + 1][0], pr2[2 * ks + 1][1]};
#pragma unroll
            for (int np = 0; np < 4; np++) {
                uint32_t vb[4];
                int row = ks * 16 + (quad & 1) * 8 + lr;
                int colb = (np * 16 + (quad >> 1) * 8) * 2;
                ldsm_x4_t(vb, sV + SW128(row * 128 + colb));
                mma_f16(oacc[np * 2], af, &vb[0]);
                mma_f16(oacc[np * 2 + 1], af, &vb[2]);
            }
        }

        if (s + 2 <= s1) {
            __syncthreads();
            stageKV(s + 2, s & 1);
            cp_commit();
        }
    }

    // write unnormalized partials + (m, l)
    float* po = split ? g_po1 : g_po0;
    float* pm = split ? g_pm1 : g_pm0;
    float* pl = split ? g_pl1 : g_pl0;
#pragma unroll
    for (int nt = 0; nt < 8; nt++) {
        int col = h * HD + nt * 8 + 2 * tq;
        *(float2*)&po[(size_t)(qt * 64 + row0) * (NH * HD) + col] =
            make_float2(oacc[nt][0], oacc[nt][1]);
        *(float2*)&po[(size_t)(qt * 64 + row1) * (NH * HD) + col] =
            make_float2(oacc[nt][2], oacc[nt][3]);
    }
    if (tq == 0) {
        pm[(qt * 64 + row0) * NH + h] = m0;
        pl[(qt * 64 + row0) * NH + h] = l0;
        pm[(qt * 64 + row1) * NH + h] = m1;
        pl[(qt * 64 + row1) * NH + h] = l1;
    }
}

// ---------------------------------------------------------------------------
// Combine split-KV partials -> fp16 attention output.
// ---------------------------------------------------------------------------
__global__ __launch_bounds__(256) void attn_combine(__half* __restrict__ out) {
    const size_t base = ((size_t)blockIdx.x * 256 + threadIdx.x) * 4;
    const int t = (int)(base >> 11);       // /2048
    const int col = (int)(base & 2047);
    const int h = col >> 6;
    const int qt = t >> 6;

    float4 o0 = *(float4*)&g_po0[base];
    float m0 = g_pm0[t * NH + h];
    float l0 = g_pl0[t * NH + h];
    float rx, ry, rz, rw;
    if (qt >= 8) {
        float4 o1 = *(float4*)&g_po1[base];
        float m1 = g_pm1[t * NH + h];
        float l1 = g_pl1[t * NH + h];
        float m = fmaxf(m0, m1);
        float a0 = __expf(m0 - m), a1 = __expf(m1 - m);
        float inv = 1.0f / (l0 * a0 + l1 * a1);
        rx = (o0.x * a0 + o1.x * a1) * inv;
        ry = (o0.y * a0 + o1.y * a1) * inv;
        rz = (o0.z * a0 + o1.z * a1) * inv;
        rw = (o0.w * a0 + o1.w * a1) * inv;
    } else {
        float inv = 1.0f / l0;
        rx = o0.x * inv; ry = o0.y * inv;
        rz = o0.z * inv; rw = o0.w * inv;
    }
    *(__half2*)&out[base]     = __floats2half2_rn(rx, ry);
    *(__half2*)&out[base + 2] = __floats2half2_rn(rz, rw);
}

// ---------------------------------------------------------------------------
// Inputs: 0=x 1=scale_x 2=mask 3=cos 4=scale_cos 5=sin 6=scale_sin
//         7=Wq 8=Wk 9=Wv 10=Wo 11=q_norm_w 12=k_norm_w
// ---------------------------------------------------------------------------
extern "C" void kernel_launch(void* const* d_in, const int* in_sizes, int n_in,
                              void* d_out, int out_size) {
    const float* x    = (const float*)d_in[0];
    const float* cosb = (const float*)d_in[3];
    const float* sinb = (const float*)d_in[5];
    const float* Wq   = (const float*)d_in[7];
    const float* Wk   = (const float*)d_in[8];
    const float* Wv   = (const float*)d_in[9];
    const float* Wo   = (const float*)d_in[10];
    const float* qw   = (const float*)d_in[11];
    const float* kw   = (const float*)d_in[12];
    float* out = (float*)d_out;

    float *qb, *kb;
    __half *abh, *woh;
    cudaGetSymbolAddress((void**)&qb, g_q);
    cudaGetSymbolAddress((void**)&kb, g_k);
    cudaGetSymbolAddress((void**)&abh, g_abh);
    cudaGetSymbolAddress((void**)&woh, g_woh);

    const int gsmem = 65536;
    cudaFuncSetAttribute(gemm_qkv_h,
                         cudaFuncAttributeMaxDynamicSharedMemorySize, gsmem);
    cudaFuncSetAttribute(gemm_h,
                         cudaFuncAttributeMaxDynamicSharedMemorySize, gsmem);
    const int asmem = 8192 + 2 * 16384;
    cudaFuncSetAttribute(attn_h,
                         cudaFuncAttributeMaxDynamicSharedMemorySize, asmem);

    // fp32 -> fp16 conversion (x + all weights)
    cvt_all<<<6144, 256>>>(x, Wq, Wk, Wv, Wo);

    // Fused QKV projection (V straight to fp16)
    gemm_qkv_h<<<dim3(24, 8), 256, gsmem>>>(qb, kb);

    // RMSNorm + RoPE -> fp16 q (pre-scaled), fp16 k
    norm_rope2<<<dim3(T_TOK, 5), 256>>>(qb, kb, qw, kw, cosb, sinb);

    // Split-KV fp16 flash attention + combine
    attn_h<<<dim3(2, 32, 16), 128, asmem>>>();
    attn_combine<<<2048, 256>>>(abh);

    // Output projection
    gemm_h<<<dim3(16, 8), 256, gsmem>>>(abh, woh, out, DIN, NH * HD);
}

// round 11
// speedup vs baseline: 1.0194x; 1.0194x over previous
#include <cuda_runtime.h>
#include <cuda_fp16.h>
#include <stdint.h>
#include <math.h>

#define T_TOK 1024
#define DIN   2048
#define NH    32
#define NKV   8
#define HD    64

__device__ __half g_q16[T_TOK * NH * HD];  // raw q from GEMM (fp16)
__device__ __half g_k16[T_TOK * NKV * HD];
__device__ __half g_qa[T_TOK * NH * HD];   // normed+roped q (scaled 0.125)
__device__ __half g_ka[T_TOK * NKV * HD];
__device__ __half g_va[T_TOK * NKV * HD];
__device__ __half g_xh[T_TOK * DIN];
__device__ __half g_wqh[NH * HD * DIN];
__device__ __half g_wkh[NKV * HD * DIN];
__device__ __half g_wvh[NKV * HD * DIN];
__device__ __half g_woh[DIN * NH * HD];
__device__ __half g_abh[T_TOK * NH * HD];
// split-KV partials (only tokens >= 512 use them)
__device__ float g_po0[T_TOK * NH * HD];
__device__ float g_po1[T_TOK * NH * HD];
__device__ float g_pm0[T_TOK * NH];
__device__ float g_pm1[T_TOK * NH];
__device__ float g_pl0[T_TOK * NH];
__device__ float g_pl1[T_TOK * NH];

// ---------------------------------------------------------------------------
// asm helpers
// ---------------------------------------------------------------------------
__device__ __forceinline__ uint32_t smem_u32(const void* p) {
    uint32_t a;
    asm("{ .reg .u64 t; cvta.to.shared.u64 t, %1; cvt.u32.u64 %0, t; }"
        : "=r"(a) : "l"(p));
    return a;
}

__device__ __forceinline__ void mma_f16(float* c, const uint32_t* a,
                                        const uint32_t* b) {
    asm volatile(
        "mma.sync.aligned.m16n8k16.row.col.f32.f16.f16.f32 "
        "{%0,%1,%2,%3},{%4,%5,%6,%7},{%8,%9},{%0,%1,%2,%3};"
        : "+f"(c[0]), "+f"(c[1]), "+f"(c[2]), "+f"(c[3])
        : "r"(a[0]), "r"(a[1]), "r"(a[2]), "r"(a[3]), "r"(b[0]), "r"(b[1]));
}

__device__ __forceinline__ void ldsm_x4(uint32_t* r, uint32_t addr) {
    asm volatile(
        "ldmatrix.sync.aligned.m8n8.x4.shared.b16 {%0,%1,%2,%3}, [%4];"
        : "=r"(r[0]), "=r"(r[1]), "=r"(r[2]), "=r"(r[3]) : "r"(addr));
}

__device__ __forceinline__ void ldsm_x4_t(uint32_t* r, uint32_t addr) {
    asm volatile(
        "ldmatrix.sync.aligned.m8n8.x4.trans.shared.b16 {%0,%1,%2,%3}, [%4];"
        : "=r"(r[0]), "=r"(r[1]), "=r"(r[2]), "=r"(r[3]) : "r"(addr));
}

__device__ __forceinline__ void cp16(uint32_t d, const void* s) {
    asm volatile("cp.async.cg.shared.global [%0], [%1], 16;"
                 :: "r"(d), "l"(s));
}
__device__ __forceinline__ void cp_commit() {
    asm volatile("cp.async.commit_group;");
}
template <int N>
__device__ __forceinline__ void cp_wait() {
    asm volatile("cp.async.wait_group %0;" :: "n"(N));
}

__device__ __forceinline__ uint32_t h2pack(float a, float b) {
    __half2 h = __floats2half2_rn(a, b);
    return *(uint32_t*)&h;
}

#define SW128(o) ((o) ^ (((o) >> 3) & 0x70))

// ---------------------------------------------------------------------------
// fp32 -> fp16 convert (x, Wq, Wk, Wv, Wo): 12M elems, 8 per thread.
// ---------------------------------------------------------------------------
__global__ __launch_bounds__(256) void cvt_all(const float* __restrict__ x,
                                               const float* __restrict__ Wq,
                                               const float* __restrict__ Wk,
                                               const float* __restrict__ Wv,
                                               const float* __restrict__ Wo) {
    const size_t e = ((size_t)blockIdx.x * 256 + threadIdx.x) * 8;
    const float* src;
    __half* dst;
    size_t base;
    if (e < 2097152)        { src = x;  dst = g_xh;  base = 0; }
    else if (e < 6291456)   { src = Wq; dst = g_wqh; base = 2097152; }
    else if (e < 7340032)   { src = Wk; dst = g_wkh; base = 6291456; }
    else if (e < 8388608)   { src = Wv; dst = g_wvh; base = 7340032; }
    else                    { src = Wo; dst = g_woh; base = 8388608; }
    const size_t o = e - base;
#pragma unroll
    for (int p = 0; p < 2; p++) {
        float4 v = *(const float4*)&src[o + p * 4];
        *(__half2*)&dst[o + p * 4]     = __floats2half2_rn(v.x, v.y);
        *(__half2*)&dst[o + p * 4 + 2] = __floats2half2_rn(v.z, v.w);
    }
}

// ---------------------------------------------------------------------------
// fp16 GEMM via cp.async + ldmatrix (2-stage, 64KB).
// ---------------------------------------------------------------------------
__device__ __forceinline__ void gemm_tile_h(const __half* __restrict__ A,
                                            const __half* __restrict__ B,
                                            float* __restrict__ C,
                                            __half* __restrict__ Ch,
                                            int N, int K, int bm, int bn,
                                            char* smem) {
    const uint32_t sbase = smem_u32(smem);
    const int tid  = threadIdx.x;
    const int lane = tid & 31;
    const int warp = tid >> 5;
    const int g    = lane >> 2;
    const int tq   = lane & 3;
    const int wm   = warp & 1;
    const int wn   = warp >> 1;
    const int quad = lane >> 3;
    const int lr   = lane & 7;
    const int ldrow = tid >> 3;
    const int ldc16 = tid & 7;

    auto stage = [&](int k0, int buf) {
        uint32_t dA = sbase + buf * 32768;
        uint32_t dB = dA + 16384;
#pragma unroll
        for (int p = 0; p < 4; p++) {
            int r = ldrow + p * 32;
            cp16(dA + SW128(r * 128 + ldc16 * 16),
                 &A[(size_t)(bm + r) * K + k0 + ldc16 * 8]);
            cp16(dB + SW128(r * 128 + ldc16 * 16),
                 &B[(size_t)(bn + r) * K + k0 + ldc16 * 8]);
        }
    };

    float acc[4][4][4];
#pragma unroll
    for (int mi = 0; mi < 4; mi++)
#pragma unroll
        for (int ni = 0; ni < 4; ni++)
#pragma unroll
            for (int r = 0; r < 4; r++) acc[mi][ni][r] = 0.0f;

    stage(0, 0);
    cp_commit();
    stage(64, 1);
    cp_commit();

    const int nch = K >> 6;
    for (int c = 0; c < nch; c++) {
        if (c == nch - 1) cp_wait<0>(); else cp_wait<1>();
        __syncthreads();
        const uint32_t sA = sbase + (c & 1) * 32768;
        const uint32_t sB = sA + 16384;

#pragma unroll
        for (int ks = 0; ks < 4; ks++) {
            uint32_t af[4][4];
#pragma unroll
            for (int mi = 0; mi < 4; mi++) {
                int row = wm * 64 + mi * 16 + (quad & 1) * 8 + lr;
                int colb = ks * 32 + (quad >> 1) * 16;
                ldsm_x4(af[mi], sA + SW128(row * 128 + colb));
            }
            uint32_t bf[2][4];
#pragma unroll
            for (int np = 0; np < 2; np++) {
                int row = wn * 32 + np * 16 + (quad >> 1) * 8 + lr;
                int colb = ks * 32 + (quad & 1) * 16;
                ldsm_x4(bf[np], sB + SW128(row * 128 + colb));
            }
#pragma unroll
            for (int mi = 0; mi < 4; mi++)
#pragma unroll
                for (int ni = 0; ni < 4; ni++)
                    mma_f16(acc[mi][ni], af[mi], &bf[ni >> 1][(ni & 1) * 2]);
        }

        if (c + 2 < nch) {
            __syncthreads();
            stage((c + 2) << 6, c & 1);
            cp_commit();
        }
    }

#pragma unroll
    for (int mi = 0; mi < 4; mi++)
#pragma unroll
        for (int ni = 0; ni < 4; ni++) {
            const int row = bm + wm * 64 + mi * 16 + g;
            const int col = bn + wn * 32 + ni * 8 + tq * 2;
            if (Ch) {
                *(__half2*)&Ch[(size_t)row * N + col] =
                    __floats2half2_rn(acc[mi][ni][0], acc[mi][ni][1]);
                *(__half2*)&Ch[(size_t)(row + 8) * N + col] =
                    __floats2half2_rn(acc[mi][ni][2], acc[mi][ni][3]);
            } else {
                *(float2*)&C[(size_t)row * N + col] =
                    make_float2(acc[mi][ni][0], acc[mi][ni][1]);
                *(float2*)&C[(size_t)(row + 8) * N + col] =
                    make_float2(acc[mi][ni][2], acc[mi][ni][3]);
            }
        }
}

__global__ __launch_bounds__(256) void gemm_h(const __half* __restrict__ A,
                                              const __half* __restrict__ B,
                                              float* __restrict__ C,
                                              int N, int K) {
    extern __shared__ char sh[];
    gemm_tile_h(A, B, C, nullptr, N, K, blockIdx.y * 128, blockIdx.x * 128, sh);
}

// Fused QKV, all outputs fp16: bx<16 -> q, bx<20 -> k, else v
__global__ __launch_bounds__(256) void gemm_qkv_h() {
    extern __shared__ char sh[];
    const int bx = blockIdx.x;
    const __half* B;
    __half* Ch;
    int N, bn;
    if (bx < 16)      { B = g_wqh; Ch = g_q16; N = 2048; bn = bx * 128; }
    else if (bx < 20) { B = g_wkh; Ch = g_k16; N = 512;  bn = (bx - 16) * 128; }
    else              { B = g_wvh; Ch = g_va;  N = 512;  bn = (bx - 20) * 128; }
    gemm_tile_h(g_xh, B, nullptr, Ch, N, 2048, blockIdx.y * 128, bn, sh);
}

// ---------------------------------------------------------------------------
// RMSNorm + RoPE; fp16 in, fp16 out (q scaled by 1/8).
// ---------------------------------------------------------------------------
__global__ __launch_bounds__(256) void norm_rope2(const float* __restrict__ qw,
                                                  const float* __restrict__ kw,
                                                  const float* __restrict__ cosb,
                                                  const float* __restrict__ sinb) {
    const int t = blockIdx.x;
    const int warp = threadIdx.x >> 5;
    const int lane = threadIdx.x & 31;
    const bool isk = (blockIdx.y == 4);
    const int h = isk ? warp : blockIdx.y * 8 + warp;
    const int nheads = isk ? NKV : NH;
    const float* w = isk ? kw : qw;
    const __half* buf = isk ? g_k16 : g_q16;
    __half* outh = isk ? g_ka : g_qa;
    const float sc = isk ? 1.0f : 0.125f;

    const __half* p = buf + (size_t)t * nheads * HD + h * HD;
    float a = __half2float(p[lane]);
    float b = __half2float(p[lane + 32]);

    float ss = a * a + b * b;
#pragma unroll
    for (int o = 16; o; o >>= 1) ss += __shfl_xor_sync(0xffffffffu, ss, o);
    float inv = rsqrtf(ss * (1.0f / HD) + 1e-6f);

    a *= inv * w[lane];
    b *= inv * w[lane + 32];

    float c0 = cosb[t * HD + lane];
    float s0 = sinb[t * HD + lane];
    float c1 = cosb[t * HD + lane + 32];
    float s1 = sinb[t * HD + lane + 32];

    __half* po = outh + (size_t)t * nheads * HD + h * HD;
    po[lane]      = __float2half((a * c0 - b * s0) * sc);
    po[lane + 32] = __float2half((b * c1 + a * s1) * sc);
}

// ---------------------------------------------------------------------------
// Split-KV fp16 flash attention, TWO heads per CTA (shared K/V staging).
// grid (2 splits, 16 head-pairs, 16 qtiles), 256 thr.
// Warps 0-3 -> head 2*hp, warps 4-7 -> head 2*hp+1 (same kv head).
// qt<8: split0 writes final fp16 directly. qt>=8: partials + combine.
// Smem: Q 16KB + 2 stages x 16KB = 48KB.
// ---------------------------------------------------------------------------
__global__ __launch_bounds__(256) void attn_h(__half* __restrict__ out) {
    const int split = blockIdx.x;
    const int qt = 15 - blockIdx.z;
    if (split == 1 && qt < 8) return;
    const int s0 = split ? 8 : 0;
    const int s1 = split ? qt : min(qt, 7);

    extern __shared__ char sm[];
    const uint32_t sbase = smem_u32(sm);

    const int hp = blockIdx.y;
    const int h0 = hp * 2;
    const int kvh = h0 >> 2;
    const int tid = threadIdx.x;
    const int lane = tid & 31;
    const int warp = tid >> 5;
    const int hsel = warp >> 2;
    const int h = h0 + hsel;
    const int g = lane >> 2;
    const int tq = lane & 3;
    const int quad = lane >> 3;
    const int lr = lane & 7;
    const int wr = (warp & 3) * 16;
    const int row0 = wr + g;
    const int row1 = wr + 8 + g;
    const uint32_t sQ = sbase + hsel * 8192;

    // stage both heads' Q tiles (16KB)
    {
#pragma unroll
        for (int l = 0; l < 4; l++) {
            int idx = tid + l * 256;
            int r = idx >> 3;           // 0..127: head (r>>6), row (r&63)
            int c16 = idx & 7;
            int hq = r >> 6;
            int row = r & 63;
            cp16(sbase + hq * 8192 + SW128(row * 128 + c16 * 16),
                 &g_qa[(size_t)(qt * 64 + row) * (NH * HD) +
                       (h0 + hq) * HD + c16 * 8]);
        }
    }
    cp_commit();

    auto stageKV = [&](int s, int buf) {
        uint32_t dK = sbase + 16384 + buf * 16384;
        uint32_t dV = dK + 8192;
        const __half* kp = g_ka + (size_t)(s * 64) * (NKV * HD) + kvh * HD;
        const __half* vp = g_va + (size_t)(s * 64) * (NKV * HD) + kvh * HD;
#pragma unroll
        for (int l = 0; l < 2; l++) {
            int idx = tid + l * 256;   // 0..511
            int c = idx >> 3;
            int c16 = idx & 7;
            uint32_t off = SW128(c * 128 + c16 * 16);
            cp16(dK + off, &kp[(size_t)c * (NKV * HD) + c16 * 8]);
            cp16(dV + off, &vp[(size_t)c * (NKV * HD) + c16 * 8]);
        }
    };

    stageKV(s0, s0 & 1);
    cp_commit();
    if (s0 < s1) {
        stageKV(s0 + 1, (s0 + 1) & 1);
        cp_commit();
    }

    if (s0 < s1) cp_wait<2>(); else cp_wait<1>();
    __syncthreads();
    uint32_t qf[4][4];
#pragma unroll
    for (int ks = 0; ks < 4; ks++) {
        int row = wr + (quad & 1) * 8 + lr;
        int colb = ks * 32 + (quad >> 1) * 16;
        ldsm_x4(qf[ks], sQ + SW128(row * 128 + colb));
    }

    float m0 = -1e30f, m1 = -1e30f, l0 = 0.0f, l1 = 0.0f;
    float oacc[8][4];
#pragma unroll
    for (int nt = 0; nt < 8; nt++)
#pragma unroll
        for (int r = 0; r < 4; r++) oacc[nt][r] = 0.0f;

    for (int s = s0; s <= s1; s++) {
        if (s == s1) cp_wait<0>(); else cp_wait<1>();
        __syncthreads();
        const uint32_t sK = sbase + 16384 + (s & 1) * 16384;
        const uint32_t sV = sK + 8192;

        float sa[8][4];
#pragma unroll
        for (int nt = 0; nt < 8; nt++)
#pragma unroll
            for (int r = 0; r < 4; r++) sa[nt][r] = 0.0f;
#pragma unroll
        for (int ks = 0; ks < 4; ks++) {
#pragma unroll
            for (int np = 0; np < 4; np++) {
                uint32_t kb[4];
                int row = np * 16 + (quad >> 1) * 8 + lr;
                int colb = ks * 32 + (quad & 1) * 16;
                ldsm_x4(kb, sK + SW128(row * 128 + colb));
                mma_f16(sa[np * 2], qf[ks], &kb[0]);
                mma_f16(sa[np * 2 + 1], qf[ks], &kb[2]);
            }
        }

        const bool diag = (s == qt);
        float rm0 = -1e30f, rm1 = -1e30f;
#pragma unroll
        for (int nt = 0; nt < 8; nt++) {
            int c0i = nt * 8 + 2 * tq;
            if (diag) {
#pragma unroll
                for (int j = 0; j < 2; j++) {
                    if (c0i + j > row0) sa[nt][j] = -1e30f;
                    if (c0i + j > row1) sa[nt][2 + j] = -1e30f;
                }
            }
            rm0 = fmaxf(rm0, fmaxf(sa[nt][0], sa[nt][1]));
            rm1 = fmaxf(rm1, fmaxf(sa[nt][2], sa[nt][3]));
        }
#pragma unroll
        for (int o = 1; o < 4; o <<= 1) {
            rm0 = fmaxf(rm0, __shfl_xor_sync(0xffffffffu, rm0, o));
            rm1 = fmaxf(rm1, __shfl_xor_sync(0xffffffffu, rm1, o));
        }
        float nm0 = fmaxf(m0, rm0), nm1 = fmaxf(m1, rm1);
        float cr0 = __expf(m0 - nm0), cr1 = __expf(m1 - nm1);
        m0 = nm0; m1 = nm1;
        float rs0 = 0.0f, rs1 = 0.0f;
        uint32_t pr2[8][2];
#pragma unroll
        for (int nt = 0; nt < 8; nt++) {
            float p0 = __expf(sa[nt][0] - m0);
            float p1 = __expf(sa[nt][1] - m0);
            float p2 = __expf(sa[nt][2] - m1);
            float p3 = __expf(sa[nt][3] - m1);
            rs0 += p0 + p1;
            rs1 += p2 + p3;
            pr2[nt][0] = h2pack(p0, p1);
            pr2[nt][1] = h2pack(p2, p3);
        }
#pragma unroll
        for (int o = 1; o < 4; o <<= 1) {
            rs0 += __shfl_xor_sync(0xffffffffu, rs0, o);
            rs1 += __shfl_xor_sync(0xffffffffu, rs1, o);
        }
        l0 = l0 * cr0 + rs0;
        l1 = l1 * cr1 + rs1;
#pragma unroll
        for (int nt = 0; nt < 8; nt++) {
            oacc[nt][0] *= cr0; oacc[nt][1] *= cr0;
            oacc[nt][2] *= cr1; oacc[nt][3] *= cr1;
        }

#pragma unroll
        for (int ks = 0; ks < 4; ks++) {
            uint32_t af[4] = {pr2[2 * ks][0], pr2[2 * ks][1],
                              pr2[2 * ks + 1][0], pr2[2 * ks + 1][1]};
#pragma unroll
            for (int np = 0; np < 4; np++) {
                uint32_t vb[4];
                int row = ks * 16 + (quad & 1) * 8 + lr;
                int colb = (np * 16 + (quad >> 1) * 8) * 2;
                ldsm_x4_t(vb, sV + SW128(row * 128 + colb));
                mma_f16(oacc[np * 2], af, &vb[0]);
                mma_f16(oacc[np * 2 + 1], af, &vb[2]);
            }
        }

        if (s + 2 <= s1) {
            __syncthreads();
            stageKV(s + 2, s & 1);
            cp_commit();
        }
    }

    if (qt < 8) {
        // single split covers everything: write final fp16 directly
        float inv0 = 1.0f / l0, inv1 = 1.0f / l1;
#pragma unroll
        for (int nt = 0; nt < 8; nt++) {
            int col = h * HD + nt * 8 + 2 * tq;
            *(__half2*)&out[(size_t)(qt * 64 + row0) * (NH * HD) + col] =
                __floats2half2_rn(oacc[nt][0] * inv0, oacc[nt][1] * inv0);
            *(__half2*)&out[(size_t)(qt * 64 + row1) * (NH * HD) + col] =
                __floats2half2_rn(oacc[nt][2] * inv1, oacc[nt][3] * inv1);
        }
    } else {
        float* po = split ? g_po1 : g_po0;
        float* pm = split ? g_pm1 : g_pm0;
        float* pl = split ? g_pl1 : g_pl0;
#pragma unroll
        for (int nt = 0; nt < 8; nt++) {
            int col = h * HD + nt * 8 + 2 * tq;
            *(float2*)&po[(size_t)(qt * 64 + row0) * (NH * HD) + col] =
                make_float2(oacc[nt][0], oacc[nt][1]);
            *(float2*)&po[(size_t)(qt * 64 + row1) * (NH * HD) + col] =
                make_float2(oacc[nt][2], oacc[nt][3]);
        }
        if (tq == 0) {
            pm[(qt * 64 + row0) * NH + h] = m0;
            pl[(qt * 64 + row0) * NH + h] = l0;
            pm[(qt * 64 + row1) * NH + h] = m1;
            pl[(qt * 64 + row1) * NH + h] = l1;
        }
    }
}

// ---------------------------------------------------------------------------
// Combine split-KV partials (tokens 512..1023 only) -> fp16.
// ---------------------------------------------------------------------------
__global__ __launch_bounds__(256) void attn_combine(__half* __restrict__ out) {
    const size_t base = 1048576 + ((size_t)blockIdx.x * 256 + threadIdx.x) * 4;
    const int t = (int)(base >> 11);
    const int col = (int)(base & 2047);
    const int h = col >> 6;

    float4 o0 = *(float4*)&g_po0[base];
    float4 o1 = *(float4*)&g_po1[base];
    float m0 = g_pm0[t * NH + h];
    float l0 = g_pl0[t * NH + h];
    float m1 = g_pm1[t * NH + h];
    float l1 = g_pl1[t * NH + h];
    float m = fmaxf(m0, m1);
    float a0 = __expf(m0 - m), a1 = __expf(m1 - m);
    float inv = 1.0f / (l0 * a0 + l1 * a1);
    *(__half2*)&out[base] = __floats2half2_rn((o0.x * a0 + o1.x * a1) * inv,
                                              (o0.y * a0 + o1.y * a1) * inv);
    *(__half2*)&out[base + 2] =
        __floats2half2_rn((o0.z * a0 + o1.z * a1) * inv,
                          (o0.w * a0 + o1.w * a1) * inv);
}

// ---------------------------------------------------------------------------
// Inputs: 0=x 1=scale_x 2=mask 3=cos 4=scale_cos 5=sin 6=scale_sin
//         7=Wq 8=Wk 9=Wv 10=Wo 11=q_norm_w 12=k_norm_w
// ---------------------------------------------------------------------------
extern "C" void kernel_launch(void* const* d_in, const int* in_sizes, int n_in,
                              void* d_out, int out_size) {
    const float* x    = (const float*)d_in[0];
    const float* cosb = (const float*)d_in[3];
    const float* sinb = (const float*)d_in[5];
    const float* Wq   = (const float*)d_in[7];
    const float* Wk   = (const float*)d_in[8];
    const float* Wv   = (const float*)d_in[9];
    const float* Wo   = (const float*)d_in[10];
    const float* qw   = (const float*)d_in[11];
    const float* kw   = (const float*)d_in[12];
    float* out = (float*)d_out;

    __half *abh, *woh;
    cudaGetSymbolAddress((void**)&abh, g_abh);
    cudaGetSymbolAddress((void**)&woh, g_woh);

    const int gsmem = 65536;
    cudaFuncSetAttribute(gemm_qkv_h,
                         cudaFuncAttributeMaxDynamicSharedMemorySize, gsmem);
    cudaFuncSetAttribute(gemm_h,
                         cudaFuncAttributeMaxDynamicSharedMemorySize, gsmem);
    const int asmem = 16384 + 2 * 16384;  // 2 Q heads + 2 KV stages = 48KB
    cudaFuncSetAttribute(attn_h,
                         cudaFuncAttributeMaxDynamicSharedMemorySize, asmem);

    // fp32 -> fp16 conversion (x + all weights)
    cvt_all<<<6144, 256>>>(x, Wq, Wk, Wv, Wo);

    // Fused QKV projection (all outputs fp16)
    gemm_qkv_h<<<dim3(24, 8), 256, gsmem>>>();

    // RMSNorm + RoPE (fp16 in/out)
    norm_rope2<<<dim3(T_TOK, 5), 256>>>(qw, kw, cosb, sinb);

    // Split-KV fp16 flash attention (2 heads/CTA) + combine (t>=512 only)
    attn_h<<<dim3(2, 16, 16), 256, asmem>>>(abh);
    attn_combine<<<1024, 256>>>(abh);

    // Output projection
    gemm_h<<<dim3(16, 8), 256, gsmem>>>(abh, woh, out, DIN, NH * HD);
}